// round 6
// baseline (speedup 1.0000x reference)
#include <cuda_runtime.h>
#include <cuda_bf16.h>
#include <math.h>
#include <stdint.h>

// ---------------- problem constants ----------------
#define T_TOK   1024
#define D_DIM   2048
#define DFF_DIM 1024
#define E_EXP   16
#define K_TOP   6
#define P_PAIR  (T_TOK * K_TOP)          // 6144
#define BM      128
#define P_PAD   (P_PAIR + E_EXP * BM)    // 8192
#define MAX_TILES (P_PAD / BM)           // 64
#define KBLK    32

// smem: 4 bf16 planes (Ahi, Alo, Bhi, Blo), 128 rows x 40 bf16 (80B stride)
#define ROWSTRIDE 80
#define PLANE     10240                  // 128 * 80
#define STAGE     40960                  // 4 planes
#define SMEM_BYTES (2 * STAGE)           // 81920, double buffered

// ---------------- static device scratch ----------------
__device__ int   g_rows[P_PAD];
__device__ int   g_slot[P_PAIR];
__device__ int   g_cnt [E_EXP];
__device__ int   g_cur [E_EXP];
__device__ int   g_tile_e[MAX_TILES];
__device__ int   g_ntiles;
__device__ int   g_sel64;
__device__ __nv_bfloat16 g_Hhi[(size_t)P_PAD * DFF_DIM];   // 16 MB
__device__ __nv_bfloat16 g_Hlo[(size_t)P_PAD * DFF_DIM];   // 16 MB
__device__ float         g_Y  [(size_t)P_PAD * D_DIM];     // 64 MB

// ---------------- helpers ----------------
__device__ __forceinline__ uint32_t smem_u32(const void* p) {
    uint32_t a;
    asm("{ .reg .u64 t; cvta.to.shared.u64 t, %1; cvt.u32.u64 %0, t; }" : "=r"(a) : "l"(p));
    return a;
}

#define LDSM4(r, addr)                                                        \
    asm volatile("ldmatrix.sync.aligned.m8n8.x4.shared.b16 {%0,%1,%2,%3}, [%4];" \
        : "=r"((r)[0]), "=r"((r)[1]), "=r"((r)[2]), "=r"((r)[3]) : "r"(addr))

#define MMA(c, a, b0, b1)                                                     \
    asm volatile("mma.sync.aligned.m16n8k16.row.col.f32.bf16.bf16.f32 "       \
        "{%0,%1,%2,%3}, {%4,%5,%6,%7}, {%8,%9}, {%0,%1,%2,%3};"               \
        : "+f"((c)[0]), "+f"((c)[1]), "+f"((c)[2]), "+f"((c)[3])              \
        : "r"((a)[0]), "r"((a)[1]), "r"((a)[2]), "r"((a)[3]), "r"(b0), "r"(b1))

// 8 fp32 -> 8 bf16 hi (uint4) + 8 bf16 lo (uint4); error-free split
__device__ __forceinline__ void cvt8(float4 a, float4 b, uint4& hh, uint4& ll) {
    float f[8] = {a.x, a.y, a.z, a.w, b.x, b.y, b.z, b.w};
    uint32_t h[8], l[8];
    #pragma unroll
    for (int i = 0; i < 8; i++) {
        __nv_bfloat16 bh = __float2bfloat16(f[i]);
        __nv_bfloat16 bl = __float2bfloat16(f[i] - __bfloat162float(bh));
        h[i] = (uint32_t)__bfloat16_as_ushort(bh);
        l[i] = (uint32_t)__bfloat16_as_ushort(bl);
    }
    hh = make_uint4(h[0] | (h[1] << 16), h[2] | (h[3] << 16),
                    h[4] | (h[5] << 16), h[6] | (h[7] << 16));
    ll = make_uint4(l[0] | (l[1] << 16), l[2] | (l[3] << 16),
                    l[4] | (l[5] << 16), l[6] | (l[7] << 16));
}

// ---------------- prep0: init scratch + dtype detection ----------------
__global__ void prep0_kernel(const void* sel) {
    int i = blockIdx.x * blockDim.x + threadIdx.x;
    if (i < P_PAD) g_rows[i] = -1;
    if (i < E_EXP) { g_cnt[i] = 0; g_cur[i] = 0; }
    if (blockIdx.x == 0) {
        // int64 data: every (lo,hi) pair has hi==0 && 0<=lo<16.
        __shared__ int bad;
        if (threadIdx.x == 0) bad = 0;
        __syncthreads();
        const int* w = (const int*)sel;
        for (int j = threadIdx.x; j < 1024; j += blockDim.x) {
            int lo = w[2 * j], hi = w[2 * j + 1];
            if (hi != 0 || (unsigned)lo >= E_EXP) atomicOr(&bad, 1);
        }
        __syncthreads();
        if (threadIdx.x == 0) g_sel64 = bad ? 0 : 1;
    }
}
__device__ __forceinline__ int load_expert(const void* sel, int p) {
    int e = g_sel64 ? (int)((const long long*)sel)[p] : ((const int*)sel)[p];
    return e & (E_EXP - 1);
}

__global__ void count_kernel(const void* __restrict__ sel) {
    int p = blockIdx.x * blockDim.x + threadIdx.x;
    if (p < P_PAIR) atomicAdd(&g_cnt[load_expert(sel, p)], 1);
}

// ---------------- setup + fill (single block) ----------------
__global__ void setup_fill_kernel(const void* __restrict__ sel) {
    __shared__ int basepad[E_EXP];
    if (threadIdx.x == 0) {
        int pos = 0;
        for (int e = 0; e < E_EXP; e++) {
            basepad[e] = pos;
            int tiles = (g_cnt[e] + BM - 1) / BM;
            for (int i = 0; i < tiles; i++) g_tile_e[pos / BM + i] = e;
            pos += tiles * BM;
        }
        g_ntiles = pos / BM;
    }
    __syncthreads();
    for (int p = threadIdx.x; p < P_PAIR; p += blockDim.x) {
        int e = load_expert(sel, p);
        int idx = basepad[e] + atomicAdd(&g_cur[e], 1);
        g_rows[idx] = p / K_TOP;
        g_slot[p] = idx;
    }
}

// ---------------- GEMM1: x @ [w0|w1 interleaved]^T -> SwiGLU -> H ----------------
// grid: (tile FASTEST, bx slow) for L2 weight reuse across same-expert tiles
__global__ void __launch_bounds__(256) gemm1_mma(
    const float* __restrict__ x,  const float* __restrict__ w0,
    const float* __restrict__ w1, const float* __restrict__ s0,
    const float* __restrict__ s1)
{
    int tile = blockIdx.x;
    if (tile >= g_ntiles) return;
    int e  = g_tile_e[tile];
    int bx = blockIdx.y;                 // 64-wide dff block

    extern __shared__ char smem[];
    uint32_t sb = smem_u32(smem);
    int tid = threadIdx.x, lane = tid & 31, wid = tid >> 5;
    int wr = wid >> 2, wc = wid & 3;

    // ---- fill-side per-thread pointers: thread covers row fr, k-half fh ----
    int fr = tid >> 1, fh = tid & 1;
    int grow = g_rows[tile * BM + fr];
    const float* axp = (grow >= 0) ? x + (size_t)grow * D_DIM + fh * 16 : (const float*)0;
    int dffcol = bx * 64 + (fr >> 1);
    const float* bwp = ((fr & 1) ? w1 : w0) + ((size_t)e * DFF_DIM + dffcol) * D_DIM + fh * 16;
    uint32_t stsOff = (uint32_t)(fr * ROWSTRIDE + fh * 32);

    // ---- ldmatrix per-lane offsets ----
    int li = lane & 7;
    uint32_t offA = (uint32_t)((wr * 64 + ((lane >> 3) & 1) * 8 + li) * ROWSTRIDE
                               + ((lane >> 4) & 1) * 16);
    uint32_t offB = (uint32_t)((wc * 32 + ((lane >> 4) & 1) * 8 + li) * ROWSTRIDE
                               + ((lane >> 3) & 1) * 16);

    float acc[4][4][4];
    #pragma unroll
    for (int i = 0; i < 4; i++)
        #pragma unroll
        for (int j = 0; j < 4; j++)
            #pragma unroll
            for (int c = 0; c < 4; c++) acc[i][j][c] = 0.f;

    float4 rA[4], rB[4];
    auto ldg = [&](int k0) {
        #pragma unroll
        for (int q = 0; q < 4; q++) {
            rA[q] = axp ? *(const float4*)(axp + k0 + q * 4) : make_float4(0.f, 0.f, 0.f, 0.f);
            rB[q] = *(const float4*)(bwp + k0 + q * 4);
        }
    };
    auto sts = [&](int st) {
        char* base = smem + st * STAGE;
        uint4 hh0, ll0, hh1, ll1;
        cvt8(rA[0], rA[1], hh0, ll0); cvt8(rA[2], rA[3], hh1, ll1);
        *(uint4*)(base + 0 * PLANE + stsOff)      = hh0;
        *(uint4*)(base + 0 * PLANE + stsOff + 16) = hh1;
        *(uint4*)(base + 1 * PLANE + stsOff)      = ll0;
        *(uint4*)(base + 1 * PLANE + stsOff + 16) = ll1;
        cvt8(rB[0], rB[1], hh0, ll0); cvt8(rB[2], rB[3], hh1, ll1);
        *(uint4*)(base + 2 * PLANE + stsOff)      = hh0;
        *(uint4*)(base + 2 * PLANE + stsOff + 16) = hh1;
        *(uint4*)(base + 3 * PLANE + stsOff)      = ll0;
        *(uint4*)(base + 3 * PLANE + stsOff + 16) = ll1;
    };

    ldg(0); sts(0);
    __syncthreads();

    const int NKB = D_DIM / KBLK;   // 64
    for (int kb = 0; kb < NKB; kb++) {
        if (kb + 1 < NKB) ldg((kb + 1) * KBLK);
        uint32_t st = sb + (kb & 1) * STAGE;
        #pragma unroll
        for (int s = 0; s < 2; s++) {
            uint32_t Ah[4][4], Al[4][4], Bh[2][4], Bl[2][4];
            #pragma unroll
            for (int mi = 0; mi < 4; mi++) {
                LDSM4(Ah[mi], st + 0 * PLANE + offA + mi * 16 * ROWSTRIDE + s * 32);
                LDSM4(Al[mi], st + 1 * PLANE + offA + mi * 16 * ROWSTRIDE + s * 32);
            }
            #pragma unroll
            for (int nj = 0; nj < 2; nj++) {
                LDSM4(Bh[nj], st + 2 * PLANE + offB + nj * 16 * ROWSTRIDE + s * 32);
                LDSM4(Bl[nj], st + 3 * PLANE + offB + nj * 16 * ROWSTRIDE + s * 32);
            }
            #pragma unroll
            for (int mi = 0; mi < 4; mi++)
                #pragma unroll
                for (int nj = 0; nj < 2; nj++) {
                    MMA(acc[mi][nj*2],   Ah[mi], Bh[nj][0], Bh[nj][1]);
                    MMA(acc[mi][nj*2+1], Ah[mi], Bh[nj][2], Bh[nj][3]);
                    MMA(acc[mi][nj*2],   Ah[mi], Bl[nj][0], Bl[nj][1]);
                    MMA(acc[mi][nj*2+1], Ah[mi], Bl[nj][2], Bl[nj][3]);
                    MMA(acc[mi][nj*2],   Al[mi], Bh[nj][0], Bh[nj][1]);
                    MMA(acc[mi][nj*2+1], Al[mi], Bh[nj][2], Bh[nj][3]);
                }
        }
        if (kb + 1 < NKB) sts((kb + 1) & 1);
        __syncthreads();
    }

    // ---- epilogue: SwiGLU (gate=c even, up=c odd within thread), store H ----
    float s0e = s0[e], s1e = s1[e];
    #pragma unroll
    for (int mi = 0; mi < 4; mi++)
        #pragma unroll
        for (int nf = 0; nf < 4; nf++) {
            int r0  = tile * BM + wr * 64 + mi * 16 + (lane >> 2);
            int col = bx * 64 + wc * 16 + nf * 4 + (lane & 3);
            float g0 = acc[mi][nf][0] * s0e, u0 = acc[mi][nf][1] * s1e;
            float g8 = acc[mi][nf][2] * s0e, u8 = acc[mi][nf][3] * s1e;
            float h0 = (g0 / (1.f + __expf(-g0))) * u0;
            float h8 = (g8 / (1.f + __expf(-g8))) * u8;
            size_t o0 = (size_t)r0 * DFF_DIM + col;
            size_t o8 = o0 + (size_t)8 * DFF_DIM;
            __nv_bfloat16 b0 = __float2bfloat16(h0);
            __nv_bfloat16 b8 = __float2bfloat16(h8);
            g_Hhi[o0] = b0; g_Hlo[o0] = __float2bfloat16(h0 - __bfloat162float(b0));
            g_Hhi[o8] = b8; g_Hlo[o8] = __float2bfloat16(h8 - __bfloat162float(b8));
        }
}

// ---------------- GEMM2: H @ w2^T * s2 -> Y ----------------
// grid: (tile FASTEST, bx slow)
__global__ void __launch_bounds__(256) gemm2_mma(
    const float* __restrict__ w2, const float* __restrict__ s2)
{
    int tile = blockIdx.x;
    if (tile >= g_ntiles) return;
    int e  = g_tile_e[tile];
    int bx = blockIdx.y;                 // 128-wide d block

    extern __shared__ char smem[];
    uint32_t sb = smem_u32(smem);
    int tid = threadIdx.x, lane = tid & 31, wid = tid >> 5;
    int wr = wid >> 2, wc = wid & 3;

    int fr = tid >> 1, fh = tid & 1;
    const __nv_bfloat16* ahp = g_Hhi + (size_t)(tile * BM + fr) * DFF_DIM + fh * 16;
    const __nv_bfloat16* alp = g_Hlo + (size_t)(tile * BM + fr) * DFF_DIM + fh * 16;
    const float* bwp = w2 + ((size_t)e * D_DIM + bx * 128 + fr) * DFF_DIM + fh * 16;
    uint32_t stsOff = (uint32_t)(fr * ROWSTRIDE + fh * 32);

    int li = lane & 7;
    uint32_t offA = (uint32_t)((wr * 64 + ((lane >> 3) & 1) * 8 + li) * ROWSTRIDE
                               + ((lane >> 4) & 1) * 16);
    uint32_t offB = (uint32_t)((wc * 32 + ((lane >> 4) & 1) * 8 + li) * ROWSTRIDE
                               + ((lane >> 3) & 1) * 16);

    float acc[4][4][4];
    #pragma unroll
    for (int i = 0; i < 4; i++)
        #pragma unroll
        for (int j = 0; j < 4; j++)
            #pragma unroll
            for (int c = 0; c < 4; c++) acc[i][j][c] = 0.f;

    uint4 ha0, ha1, la0, la1;
    float4 rB[4];
    auto ldg = [&](int k0) {
        ha0 = *(const uint4*)(ahp + k0);     ha1 = *(const uint4*)(ahp + k0 + 8);
        la0 = *(const uint4*)(alp + k0);     la1 = *(const uint4*)(alp + k0 + 8);
        #pragma unroll
        for (int q = 0; q < 4; q++) rB[q] = *(const float4*)(bwp + k0 + q * 4);
    };
    auto sts = [&](int st) {
        char* base = smem + st * STAGE;
        *(uint4*)(base + 0 * PLANE + stsOff)      = ha0;
        *(uint4*)(base + 0 * PLANE + stsOff + 16) = ha1;
        *(uint4*)(base + 1 * PLANE + stsOff)      = la0;
        *(uint4*)(base + 1 * PLANE + stsOff + 16) = la1;
        uint4 hh0, ll0, hh1, ll1;
        cvt8(rB[0], rB[1], hh0, ll0); cvt8(rB[2], rB[3], hh1, ll1);
        *(uint4*)(base + 2 * PLANE + stsOff)      = hh0;
        *(uint4*)(base + 2 * PLANE + stsOff + 16) = hh1;
        *(uint4*)(base + 3 * PLANE + stsOff)      = ll0;
        *(uint4*)(base + 3 * PLANE + stsOff + 16) = ll1;
    };

    ldg(0); sts(0);
    __syncthreads();

    const int NKB = DFF_DIM / KBLK;   // 32
    for (int kb = 0; kb < NKB; kb++) {
        if (kb + 1 < NKB) ldg((kb + 1) * KBLK);
        uint32_t st = sb + (kb & 1) * STAGE;
        #pragma unroll
        for (int s = 0; s < 2; s++) {
            uint32_t Ah[4][4], Al[4][4], Bh[2][4], Bl[2][4];
            #pragma unroll
            for (int mi = 0; mi < 4; mi++) {
                LDSM4(Ah[mi], st + 0 * PLANE + offA + mi * 16 * ROWSTRIDE + s * 32);
                LDSM4(Al[mi], st + 1 * PLANE + offA + mi * 16 * ROWSTRIDE + s * 32);
            }
            #pragma unroll
            for (int nj = 0; nj < 2; nj++) {
                LDSM4(Bh[nj], st + 2 * PLANE + offB + nj * 16 * ROWSTRIDE + s * 32);
                LDSM4(Bl[nj], st + 3 * PLANE + offB + nj * 16 * ROWSTRIDE + s * 32);
            }
            #pragma unroll
            for (int mi = 0; mi < 4; mi++)
                #pragma unroll
                for (int nj = 0; nj < 2; nj++) {
                    MMA(acc[mi][nj*2],   Ah[mi], Bh[nj][0], Bh[nj][1]);
                    MMA(acc[mi][nj*2+1], Ah[mi], Bh[nj][2], Bh[nj][3]);
                    MMA(acc[mi][nj*2],   Ah[mi], Bl[nj][0], Bl[nj][1]);
                    MMA(acc[mi][nj*2+1], Ah[mi], Bl[nj][2], Bl[nj][3]);
                    MMA(acc[mi][nj*2],   Al[mi], Bh[nj][0], Bh[nj][1]);
                    MMA(acc[mi][nj*2+1], Al[mi], Bh[nj][2], Bh[nj][3]);
                }
        }
        if (kb + 1 < NKB) sts((kb + 1) & 1);
        __syncthreads();
    }

    float s2e = s2[e];
    #pragma unroll
    for (int mi = 0; mi < 4; mi++)
        #pragma unroll
        for (int nf = 0; nf < 4; nf++) {
            int r0  = tile * BM + wr * 64 + mi * 16 + (lane >> 2);
            int col = bx * 128 + wc * 32 + nf * 8 + 2 * (lane & 3);
            float2 v0 = make_float2(acc[mi][nf][0] * s2e, acc[mi][nf][1] * s2e);
            float2 v8 = make_float2(acc[mi][nf][2] * s2e, acc[mi][nf][3] * s2e);
            *(float2*)(g_Y + (size_t)r0 * D_DIM + col) = v0;
            *(float2*)(g_Y + (size_t)(r0 + 8) * D_DIM + col) = v8;
        }
}

// ---------------- final gather: out[t] = sum_k rw[t,k] * Y[slot(t,k)] ----------------
__global__ void gather_kernel(float* __restrict__ out, const float* __restrict__ rw) {
    int idx = blockIdx.x * blockDim.x + threadIdx.x;
    int t = idx >> 9;
    int q = (idx & 511) * 4;
    float4 acc = make_float4(0.f, 0.f, 0.f, 0.f);
    #pragma unroll
    for (int k = 0; k < K_TOP; k++) {
        int p = t * K_TOP + k;
        float w = rw[p];
        const float4 v = *(const float4*)(g_Y + (size_t)g_slot[p] * D_DIM + q);
        acc.x += w * v.x; acc.y += w * v.y; acc.z += w * v.z; acc.w += w * v.w;
    }
    *(float4*)(out + (size_t)t * D_DIM + q) = acc;
}

// ---------------- launch ----------------
extern "C" void kernel_launch(void* const* d_in, const int* in_sizes, int n_in,
                              void* d_out, int out_size) {
    const float* x   = (const float*)d_in[0];
    const float* w0  = (const float*)d_in[1];
    const float* w1  = (const float*)d_in[2];
    const float* w2  = (const float*)d_in[3];
    const float* s0  = (const float*)d_in[4];
    const float* s1  = (const float*)d_in[5];
    const float* s2  = (const float*)d_in[6];
    const void*  sel = d_in[7];
    const float* rw  = (const float*)d_in[8];
    float* out = (float*)d_out;

    cudaFuncSetAttribute(gemm1_mma, cudaFuncAttributeMaxDynamicSharedMemorySize, SMEM_BYTES);
    cudaFuncSetAttribute(gemm2_mma, cudaFuncAttributeMaxDynamicSharedMemorySize, SMEM_BYTES);

    prep0_kernel<<<(P_PAD + 255) / 256, 256>>>(sel);
    count_kernel<<<(P_PAIR + 255) / 256, 256>>>(sel);
    setup_fill_kernel<<<1, 256>>>(sel);
    // tile = blockIdx.x (fastest) so same-expert tiles are adjacent in launch
    // order -> consecutive CTAs reuse the same weight slice through L2.
    gemm1_mma<<<dim3(MAX_TILES, DFF_DIM / 64), 256, SMEM_BYTES>>>(x, w0, w1, s0, s1);
    gemm2_mma<<<dim3(MAX_TILES, D_DIM / 128), 256, SMEM_BYTES>>>(w2, s2);
    gather_kernel<<<(T_TOK * 512) / 256, 256>>>(out, rw);
}

// round 9
// speedup vs baseline: 1.5383x; 1.5383x over previous
#include <cuda_runtime.h>
#include <cuda_bf16.h>
#include <math.h>
#include <stdint.h>

// ---------------- problem constants ----------------
#define T_TOK   1024
#define D_DIM   2048
#define DFF_DIM 1024
#define E_EXP   16
#define K_TOP   6
#define P_PAIR  (T_TOK * K_TOP)          // 6144
#define BM      128
#define P_PAD   (P_PAIR + E_EXP * BM)    // 8192
#define MAX_TILES (P_PAD / BM)           // 64
#define KBLK    32

// smem stage: A planes 128 rows, B planes 64 rows, 80B row stride
#define ROWSTRIDE 80
#define A_HI 0
#define A_LO 10240
#define B_HI 20480
#define B_LO 25600
#define STAGE1 30720
#define SMEM_BYTES (2 * STAGE1)          // 61440, double buffered

// ---------------- static device scratch ----------------
__device__ int   g_rows[P_PAD];
__device__ int   g_slot[P_PAIR];
__device__ int   g_cnt [E_EXP];
__device__ int   g_cur [E_EXP];
__device__ int   g_tile_e[MAX_TILES];
__device__ int   g_ntiles;
__device__ int   g_sel64;
__device__ __nv_bfloat16 g_Hhi[(size_t)P_PAD * DFF_DIM];   // 16 MB
__device__ __nv_bfloat16 g_Hlo[(size_t)P_PAD * DFF_DIM];   // 16 MB
__device__ float         g_Y  [(size_t)P_PAD * D_DIM];     // 64 MB

// ---------------- helpers ----------------
__device__ __forceinline__ uint32_t smem_u32(const void* p) {
    uint32_t a;
    asm("{ .reg .u64 t; cvta.to.shared.u64 t, %1; cvt.u32.u64 %0, t; }" : "=r"(a) : "l"(p));
    return a;
}

#define LDSM4(r, addr)                                                        \
    asm volatile("ldmatrix.sync.aligned.m8n8.x4.shared.b16 {%0,%1,%2,%3}, [%4];" \
        : "=r"((r)[0]), "=r"((r)[1]), "=r"((r)[2]), "=r"((r)[3]) : "r"(addr))

#define MMA(c, a, b0, b1)                                                     \
    asm volatile("mma.sync.aligned.m16n8k16.row.col.f32.bf16.bf16.f32 "       \
        "{%0,%1,%2,%3}, {%4,%5,%6,%7}, {%8,%9}, {%0,%1,%2,%3};"               \
        : "+f"((c)[0]), "+f"((c)[1]), "+f"((c)[2]), "+f"((c)[3])              \
        : "r"((a)[0]), "r"((a)[1]), "r"((a)[2]), "r"((a)[3]), "r"(b0), "r"(b1))

// 8 fp32 -> 8 bf16 hi (uint4) + 8 bf16 lo (uint4); error-free split
__device__ __forceinline__ void cvt8(float4 a, float4 b, uint4& hh, uint4& ll) {
    float f[8] = {a.x, a.y, a.z, a.w, b.x, b.y, b.z, b.w};
    uint32_t h[8], l[8];
    #pragma unroll
    for (int i = 0; i < 8; i++) {
        __nv_bfloat16 bh = __float2bfloat16(f[i]);
        __nv_bfloat16 bl = __float2bfloat16(f[i] - __bfloat162float(bh));
        h[i] = (uint32_t)__bfloat16_as_ushort(bh);
        l[i] = (uint32_t)__bfloat16_as_ushort(bl);
    }
    hh = make_uint4(h[0] | (h[1] << 16), h[2] | (h[3] << 16),
                    h[4] | (h[5] << 16), h[6] | (h[7] << 16));
    ll = make_uint4(l[0] | (l[1] << 16), l[2] | (l[3] << 16),
                    l[4] | (l[5] << 16), l[6] | (l[7] << 16));
}

// ---------------- prep0: init scratch + dtype detection ----------------
__global__ void prep0_kernel(const void* sel) {
    int i = blockIdx.x * blockDim.x + threadIdx.x;
    if (i < P_PAD) g_rows[i] = -1;
    if (i < E_EXP) { g_cnt[i] = 0; g_cur[i] = 0; }
    if (blockIdx.x == 0) {
        __shared__ int bad;
        if (threadIdx.x == 0) bad = 0;
        __syncthreads();
        const int* w = (const int*)sel;
        for (int j = threadIdx.x; j < 1024; j += blockDim.x) {
            int lo = w[2 * j], hi = w[2 * j + 1];
            if (hi != 0 || (unsigned)lo >= E_EXP) atomicOr(&bad, 1);
        }
        __syncthreads();
        if (threadIdx.x == 0) g_sel64 = bad ? 0 : 1;
    }
}
__device__ __forceinline__ int load_expert(const void* sel, int p) {
    int e = g_sel64 ? (int)((const long long*)sel)[p] : ((const int*)sel)[p];
    return e & (E_EXP - 1);
}

__global__ void count_kernel(const void* __restrict__ sel) {
    int p = blockIdx.x * blockDim.x + threadIdx.x;
    if (p < P_PAIR) atomicAdd(&g_cnt[load_expert(sel, p)], 1);
}

__global__ void setup_fill_kernel(const void* __restrict__ sel) {
    __shared__ int basepad[E_EXP];
    if (threadIdx.x == 0) {
        int pos = 0;
        for (int e = 0; e < E_EXP; e++) {
            basepad[e] = pos;
            int tiles = (g_cnt[e] + BM - 1) / BM;
            for (int i = 0; i < tiles; i++) g_tile_e[pos / BM + i] = e;
            pos += tiles * BM;
        }
        g_ntiles = pos / BM;
    }
    __syncthreads();
    for (int p = threadIdx.x; p < P_PAIR; p += blockDim.x) {
        int e = load_expert(sel, p);
        int idx = basepad[e] + atomicAdd(&g_cur[e], 1);
        g_rows[idx] = p / K_TOP;
        g_slot[p] = idx;
    }
}

// ---------------- GEMM1: x @ [w0|w1 interleaved]^T -> SwiGLU -> H ----------------
// CTA 128 rows x 64 interleaved n (= 32 dff cols). grid (bx fastest, tile slow).
// Warp grid 4 (rows) x 2 (cols): warp tile 32 x 32.
__global__ void __launch_bounds__(256, 2) gemm1_mma(
    const float* __restrict__ x,  const float* __restrict__ w0,
    const float* __restrict__ w1, const float* __restrict__ s0,
    const float* __restrict__ s1)
{
    int tile = blockIdx.y;
    if (tile >= g_ntiles) return;
    int e  = g_tile_e[tile];
    int bx = blockIdx.x;

    extern __shared__ char smem[];
    uint32_t sb = smem_u32(smem);
    int tid = threadIdx.x, lane = tid & 31, wid = tid >> 5;
    int wr = wid >> 1, wc = wid & 1;

    // ---- fill-side pointers ----
    int fr = tid >> 1, fh = tid & 1;           // A: 128 rows x 2 k-halves
    int grow = g_rows[tile * BM + fr];
    const float* axp = (grow >= 0) ? x + (size_t)grow * D_DIM + fh * 16 : (const float*)0;
    int rb = tid >> 2, kq = tid & 3;           // B: 64 rows x 4 k-quarters
    int dffcol = bx * 32 + (rb >> 1);
    const float* bwp = ((rb & 1) ? w1 : w0) + ((size_t)e * DFF_DIM + dffcol) * D_DIM + kq * 8;
    uint32_t stsA = (uint32_t)(fr * ROWSTRIDE + fh * 32);
    uint32_t stsB = (uint32_t)(rb * ROWSTRIDE + kq * 16);

    // ---- ldmatrix per-lane offsets ----
    int li = lane & 7;
    uint32_t offA = (uint32_t)((wr * 32 + ((lane >> 3) & 1) * 8 + li) * ROWSTRIDE
                               + ((lane >> 4) & 1) * 16);
    uint32_t offB = (uint32_t)((wc * 32 + ((lane >> 4) & 1) * 8 + li) * ROWSTRIDE
                               + ((lane >> 3) & 1) * 16);

    float acc[2][4][4];
    #pragma unroll
    for (int i = 0; i < 2; i++)
        #pragma unroll
        for (int j = 0; j < 4; j++)
            #pragma unroll
            for (int c = 0; c < 4; c++) acc[i][j][c] = 0.f;

    float4 rA[4], rB[2];
    auto ldg = [&](int k0) {
        #pragma unroll
        for (int q = 0; q < 4; q++)
            rA[q] = axp ? *(const float4*)(axp + k0 + q * 4) : make_float4(0.f, 0.f, 0.f, 0.f);
        rB[0] = *(const float4*)(bwp + k0);
        rB[1] = *(const float4*)(bwp + k0 + 4);
    };
    auto sts = [&](int st) {
        char* base = smem + st * STAGE1;
        uint4 hh0, ll0, hh1, ll1;
        cvt8(rA[0], rA[1], hh0, ll0); cvt8(rA[2], rA[3], hh1, ll1);
        *(uint4*)(base + A_HI + stsA)      = hh0;
        *(uint4*)(base + A_HI + stsA + 16) = hh1;
        *(uint4*)(base + A_LO + stsA)      = ll0;
        *(uint4*)(base + A_LO + stsA + 16) = ll1;
        cvt8(rB[0], rB[1], hh0, ll0);
        *(uint4*)(base + B_HI + stsB) = hh0;
        *(uint4*)(base + B_LO + stsB) = ll0;
    };

    ldg(0); sts(0);
    __syncthreads();

    const int NKB = D_DIM / KBLK;   // 64
    for (int kb = 0; kb < NKB; kb++) {
        if (kb + 1 < NKB) ldg((kb + 1) * KBLK);
        uint32_t st = sb + (kb & 1) * STAGE1;
        #pragma unroll
        for (int s = 0; s < 2; s++) {
            uint32_t Ah[2][4], Al[2][4], Bh[2][4], Bl[2][4];
            #pragma unroll
            for (int mi = 0; mi < 2; mi++) {
                LDSM4(Ah[mi], st + A_HI + offA + mi * 16 * ROWSTRIDE + s * 32);
                LDSM4(Al[mi], st + A_LO + offA + mi * 16 * ROWSTRIDE + s * 32);
            }
            #pragma unroll
            for (int nj = 0; nj < 2; nj++) {
                LDSM4(Bh[nj], st + B_HI + offB + nj * 16 * ROWSTRIDE + s * 32);
                LDSM4(Bl[nj], st + B_LO + offB + nj * 16 * ROWSTRIDE + s * 32);
            }
            #pragma unroll
            for (int mi = 0; mi < 2; mi++)
                #pragma unroll
                for (int nj = 0; nj < 2; nj++) {
                    MMA(acc[mi][nj*2],   Ah[mi], Bh[nj][0], Bh[nj][1]);
                    MMA(acc[mi][nj*2+1], Ah[mi], Bh[nj][2], Bh[nj][3]);
                    MMA(acc[mi][nj*2],   Ah[mi], Bl[nj][0], Bl[nj][1]);
                    MMA(acc[mi][nj*2+1], Ah[mi], Bl[nj][2], Bl[nj][3]);
                    MMA(acc[mi][nj*2],   Al[mi], Bh[nj][0], Bh[nj][1]);
                    MMA(acc[mi][nj*2+1], Al[mi], Bh[nj][2], Bh[nj][3]);
                }
        }
        if (kb + 1 < NKB) sts((kb + 1) & 1);
        __syncthreads();
    }

    // ---- epilogue: SwiGLU (c0=gate, c1=up of same dffcol), store H hi/lo ----
    float s0e = s0[e], s1e = s1[e];
    #pragma unroll
    for (int mi = 0; mi < 2; mi++)
        #pragma unroll
        for (int nf = 0; nf < 4; nf++) {
            int r0  = tile * BM + wr * 32 + mi * 16 + (lane >> 2);
            int col = bx * 32 + wc * 16 + nf * 4 + (lane & 3);
            float g0 = acc[mi][nf][0] * s0e, u0 = acc[mi][nf][1] * s1e;
            float g8 = acc[mi][nf][2] * s0e, u8 = acc[mi][nf][3] * s1e;
            float h0 = (g0 / (1.f + __expf(-g0))) * u0;
            float h8 = (g8 / (1.f + __expf(-g8))) * u8;
            size_t o0 = (size_t)r0 * DFF_DIM + col;
            size_t o8 = o0 + (size_t)8 * DFF_DIM;
            __nv_bfloat16 b0 = __float2bfloat16(h0);
            __nv_bfloat16 b8 = __float2bfloat16(h8);
            g_Hhi[o0] = b0; g_Hlo[o0] = __float2bfloat16(h0 - __bfloat162float(b0));
            g_Hhi[o8] = b8; g_Hlo[o8] = __float2bfloat16(h8 - __bfloat162float(b8));
        }
}

// ---------------- GEMM2: H @ w2^T * s2 -> Y ----------------
// CTA 128 rows x 64 d-cols. Warp grid 4x2, warp tile 32x32.
__global__ void __launch_bounds__(256, 2) gemm2_mma(
    const float* __restrict__ w2, const float* __restrict__ s2)
{
    int tile = blockIdx.y;
    if (tile >= g_ntiles) return;
    int e  = g_tile_e[tile];
    int bx = blockIdx.x;

    extern __shared__ char smem[];
    uint32_t sb = smem_u32(smem);
    int tid = threadIdx.x, lane = tid & 31, wid = tid >> 5;
    int wr = wid >> 1, wc = wid & 1;

    int fr = tid >> 1, fh = tid & 1;
    const __nv_bfloat16* ahp = g_Hhi + (size_t)(tile * BM + fr) * DFF_DIM + fh * 16;
    const __nv_bfloat16* alp = g_Hlo + (size_t)(tile * BM + fr) * DFF_DIM + fh * 16;
    int rb = tid >> 2, kq = tid & 3;
    const float* bwp = w2 + ((size_t)e * D_DIM + bx * 64 + rb) * DFF_DIM + kq * 8;
    uint32_t stsA = (uint32_t)(fr * ROWSTRIDE + fh * 32);
    uint32_t stsB = (uint32_t)(rb * ROWSTRIDE + kq * 16);

    int li = lane & 7;
    uint32_t offA = (uint32_t)((wr * 32 + ((lane >> 3) & 1) * 8 + li) * ROWSTRIDE
                               + ((lane >> 4) & 1) * 16);
    uint32_t offB = (uint32_t)((wc * 32 + ((lane >> 4) & 1) * 8 + li) * ROWSTRIDE
                               + ((lane >> 3) & 1) * 16);

    float acc[2][4][4];
    #pragma unroll
    for (int i = 0; i < 2; i++)
        #pragma unroll
        for (int j = 0; j < 4; j++)
            #pragma unroll
            for (int c = 0; c < 4; c++) acc[i][j][c] = 0.f;

    uint4 ha0, ha1, la0, la1;
    float4 rB[2];
    auto ldg = [&](int k0) {
        ha0 = *(const uint4*)(ahp + k0);  ha1 = *(const uint4*)(ahp + k0 + 8);
        la0 = *(const uint4*)(alp + k0);  la1 = *(const uint4*)(alp + k0 + 8);
        rB[0] = *(const float4*)(bwp + k0);
        rB[1] = *(const float4*)(bwp + k0 + 4);
    };
    auto sts = [&](int st) {
        char* base = smem + st * STAGE1;
        *(uint4*)(base + A_HI + stsA)      = ha0;
        *(uint4*)(base + A_HI + stsA + 16) = ha1;
        *(uint4*)(base + A_LO + stsA)      = la0;
        *(uint4*)(base + A_LO + stsA + 16) = la1;
        uint4 hh0, ll0;
        cvt8(rB[0], rB[1], hh0, ll0);
        *(uint4*)(base + B_HI + stsB) = hh0;
        *(uint4*)(base + B_LO + stsB) = ll0;
    };

    ldg(0); sts(0);
    __syncthreads();

    const int NKB = DFF_DIM / KBLK;   // 32
    for (int kb = 0; kb < NKB; kb++) {
        if (kb + 1 < NKB) ldg((kb + 1) * KBLK);
        uint32_t st = sb + (kb & 1) * STAGE1;
        #pragma unroll
        for (int s = 0; s < 2; s++) {
            uint32_t Ah[2][4], Al[2][4], Bh[2][4], Bl[2][4];
            #pragma unroll
            for (int mi = 0; mi < 2; mi++) {
                LDSM4(Ah[mi], st + A_HI + offA + mi * 16 * ROWSTRIDE + s * 32);
                LDSM4(Al[mi], st + A_LO + offA + mi * 16 * ROWSTRIDE + s * 32);
            }
            #pragma unroll
            for (int nj = 0; nj < 2; nj++) {
                LDSM4(Bh[nj], st + B_HI + offB + nj * 16 * ROWSTRIDE + s * 32);
                LDSM4(Bl[nj], st + B_LO + offB + nj * 16 * ROWSTRIDE + s * 32);
            }
            #pragma unroll
            for (int mi = 0; mi < 2; mi++)
                #pragma unroll
                for (int nj = 0; nj < 2; nj++) {
                    MMA(acc[mi][nj*2],   Ah[mi], Bh[nj][0], Bh[nj][1]);
                    MMA(acc[mi][nj*2+1], Ah[mi], Bh[nj][2], Bh[nj][3]);
                    MMA(acc[mi][nj*2],   Ah[mi], Bl[nj][0], Bl[nj][1]);
                    MMA(acc[mi][nj*2+1], Ah[mi], Bl[nj][2], Bl[nj][3]);
                    MMA(acc[mi][nj*2],   Al[mi], Bh[nj][0], Bh[nj][1]);
                    MMA(acc[mi][nj*2+1], Al[mi], Bh[nj][2], Bh[nj][3]);
                }
        }
        if (kb + 1 < NKB) sts((kb + 1) & 1);
        __syncthreads();
    }

    float s2e = s2[e];
    #pragma unroll
    for (int mi = 0; mi < 2; mi++)
        #pragma unroll
        for (int nf = 0; nf < 4; nf++) {
            int r0  = tile * BM + wr * 32 + mi * 16 + (lane >> 2);
            int col = bx * 64 + wc * 32 + nf * 8 + 2 * (lane & 3);
            float2 v0 = make_float2(acc[mi][nf][0] * s2e, acc[mi][nf][1] * s2e);
            float2 v8 = make_float2(acc[mi][nf][2] * s2e, acc[mi][nf][3] * s2e);
            *(float2*)(g_Y + (size_t)r0 * D_DIM + col) = v0;
            *(float2*)(g_Y + (size_t)(r0 + 8) * D_DIM + col) = v8;
        }
}

// ---------------- final gather: out[t] = sum_k rw[t,k] * Y[slot(t,k)] ----------------
__global__ void gather_kernel(float* __restrict__ out, const float* __restrict__ rw) {
    int idx = blockIdx.x * blockDim.x + threadIdx.x;
    int t = idx >> 9;
    int q = (idx & 511) * 4;
    float4 acc = make_float4(0.f, 0.f, 0.f, 0.f);
    #pragma unroll
    for (int k = 0; k < K_TOP; k++) {
        int p = t * K_TOP + k;
        float w = rw[p];
        const float4 v = *(const float4*)(g_Y + (size_t)g_slot[p] * D_DIM + q);
        acc.x += w * v.x; acc.y += w * v.y; acc.z += w * v.z; acc.w += w * v.w;
    }
    *(float4*)(out + (size_t)t * D_DIM + q) = acc;
}

// ---------------- launch ----------------
extern "C" void kernel_launch(void* const* d_in, const int* in_sizes, int n_in,
                              void* d_out, int out_size) {
    const float* x   = (const float*)d_in[0];
    const float* w0  = (const float*)d_in[1];
    const float* w1  = (const float*)d_in[2];
    const float* w2  = (const float*)d_in[3];
    const float* s0  = (const float*)d_in[4];
    const float* s1  = (const float*)d_in[5];
    const float* s2  = (const float*)d_in[6];
    const void*  sel = d_in[7];
    const float* rw  = (const float*)d_in[8];
    float* out = (float*)d_out;

    cudaFuncSetAttribute(gemm1_mma, cudaFuncAttributeMaxDynamicSharedMemorySize, SMEM_BYTES);
    cudaFuncSetAttribute(gemm2_mma, cudaFuncAttributeMaxDynamicSharedMemorySize, SMEM_BYTES);

    prep0_kernel<<<(P_PAD + 255) / 256, 256>>>(sel);
    count_kernel<<<(P_PAIR + 255) / 256, 256>>>(sel);
    setup_fill_kernel<<<1, 256>>>(sel);
    // R4 raster: bx fastest -> consecutive CTAs share the same tile's x rows
    // and the same expert's weights through L2.
    gemm1_mma<<<dim3(DFF_DIM / 32, MAX_TILES), 256, SMEM_BYTES>>>(x, w0, w1, s0, s1);
    gemm2_mma<<<dim3(D_DIM / 64, MAX_TILES), 256, SMEM_BYTES>>>(w2, s2);
    gather_kernel<<<(T_TOK * 512) / 256, 256>>>(out, rw);
}

// round 10
// speedup vs baseline: 1.8457x; 1.1998x over previous
#include <cuda_runtime.h>
#include <cuda_bf16.h>
#include <math.h>
#include <stdint.h>

// ---------------- problem constants ----------------
#define T_TOK   1024
#define D_DIM   2048
#define DFF_DIM 1024
#define E_EXP   16
#define K_TOP   6
#define P_PAIR  (T_TOK * K_TOP)          // 6144
#define BM      128
#define P_PAD   (P_PAIR + E_EXP * BM)    // 8192
#define MAX_TILES (P_PAD / BM)           // 64
#define KBLK    32

// smem stage: A planes 128 rows, B planes 64 rows, 80B row stride
#define ROWSTRIDE 80
#define A_HI 0
#define A_LO 10240
#define B_HI 20480
#define B_LO 25600
#define STAGE1 30720
#define SMEM_BYTES (2 * STAGE1)          // 61440, double buffered

// ---------------- static device scratch ----------------
__device__ int   g_rows[P_PAD];
__device__ int   g_slot[P_PAIR];
__device__ int   g_cnt [E_EXP];
__device__ int   g_cur [E_EXP];
__device__ int   g_tile_e[MAX_TILES];
__device__ int   g_ntiles;
__device__ int   g_sel64;
__device__ __nv_bfloat16 g_Hhi[(size_t)P_PAD * DFF_DIM];   // 16 MB
__device__ __nv_bfloat16 g_Hlo[(size_t)P_PAD * DFF_DIM];   // 16 MB
__device__ float         g_Y  [(size_t)P_PAD * D_DIM];     // 64 MB

// ---------------- helpers ----------------
__device__ __forceinline__ uint32_t smem_u32(const void* p) {
    uint32_t a;
    asm("{ .reg .u64 t; cvta.to.shared.u64 t, %1; cvt.u32.u64 %0, t; }" : "=r"(a) : "l"(p));
    return a;
}

#define LDSM4(r, addr)                                                        \
    asm volatile("ldmatrix.sync.aligned.m8n8.x4.shared.b16 {%0,%1,%2,%3}, [%4];" \
        : "=r"((r)[0]), "=r"((r)[1]), "=r"((r)[2]), "=r"((r)[3]) : "r"(addr))

#define MMA(c, a, b0, b1)                                                     \
    asm volatile("mma.sync.aligned.m16n8k16.row.col.f32.bf16.bf16.f32 "       \
        "{%0,%1,%2,%3}, {%4,%5,%6,%7}, {%8,%9}, {%0,%1,%2,%3};"               \
        : "+f"((c)[0]), "+f"((c)[1]), "+f"((c)[2]), "+f"((c)[3])              \
        : "r"((a)[0]), "r"((a)[1]), "r"((a)[2]), "r"((a)[3]), "r"(b0), "r"(b1))

// fp32x4 -> bf16 hi (uint2) + bf16 lo (uint2); error-free split
__device__ __forceinline__ void cvt4(float4 v, uint2& hh, uint2& ll) {
    float f[4] = {v.x, v.y, v.z, v.w};
    uint32_t h[4], l[4];
    #pragma unroll
    for (int i = 0; i < 4; i++) {
        __nv_bfloat16 bh = __float2bfloat16(f[i]);
        __nv_bfloat16 bl = __float2bfloat16(f[i] - __bfloat162float(bh));
        h[i] = (uint32_t)__bfloat16_as_ushort(bh);
        l[i] = (uint32_t)__bfloat16_as_ushort(bl);
    }
    hh = make_uint2(h[0] | (h[1] << 16), h[2] | (h[3] << 16));
    ll = make_uint2(l[0] | (l[1] << 16), l[2] | (l[3] << 16));
}
__device__ __forceinline__ void cvt8(float4 a, float4 b, uint4& hh, uint4& ll) {
    uint2 h0, l0, h1, l1;
    cvt4(a, h0, l0); cvt4(b, h1, l1);
    hh = make_uint4(h0.x, h0.y, h1.x, h1.y);
    ll = make_uint4(l0.x, l0.y, l1.x, l1.y);
}

// ---------------- prep0: init scratch + dtype detection ----------------
__global__ void prep0_kernel(const void* sel) {
    int i = blockIdx.x * blockDim.x + threadIdx.x;
    if (i < P_PAD) g_rows[i] = -1;
    if (i < E_EXP) { g_cnt[i] = 0; g_cur[i] = 0; }
    if (blockIdx.x == 0) {
        __shared__ int bad;
        if (threadIdx.x == 0) bad = 0;
        __syncthreads();
        const int* w = (const int*)sel;
        for (int j = threadIdx.x; j < 1024; j += blockDim.x) {
            int lo = w[2 * j], hi = w[2 * j + 1];
            if (hi != 0 || (unsigned)lo >= E_EXP) atomicOr(&bad, 1);
        }
        __syncthreads();
        if (threadIdx.x == 0) g_sel64 = bad ? 0 : 1;
    }
}
__device__ __forceinline__ int load_expert(const void* sel, int p) {
    int e = g_sel64 ? (int)((const long long*)sel)[p] : ((const int*)sel)[p];
    return e & (E_EXP - 1);
}

__global__ void count_kernel(const void* __restrict__ sel) {
    int p = blockIdx.x * blockDim.x + threadIdx.x;
    if (p < P_PAIR) atomicAdd(&g_cnt[load_expert(sel, p)], 1);
}

__global__ void setup_fill_kernel(const void* __restrict__ sel) {
    __shared__ int basepad[E_EXP];
    if (threadIdx.x == 0) {
        int pos = 0;
        for (int e = 0; e < E_EXP; e++) {
            basepad[e] = pos;
            int tiles = (g_cnt[e] + BM - 1) / BM;
            for (int i = 0; i < tiles; i++) g_tile_e[pos / BM + i] = e;
            pos += tiles * BM;
        }
        g_ntiles = pos / BM;
    }
    __syncthreads();
    for (int p = threadIdx.x; p < P_PAIR; p += blockDim.x) {
        int e = load_expert(sel, p);
        int idx = basepad[e] + atomicAdd(&g_cur[e], 1);
        g_rows[idx] = p / K_TOP;
        g_slot[p] = idx;
    }
}

// ---------------- GEMM1: x @ [w0|w1 interleaved]^T -> SwiGLU -> H ----------------
// CTA 128 rows x 64 interleaved n (= 32 dff cols). grid (bx fastest, tile slow).
// Warp grid 4 (rows) x 2 (cols): warp tile 32 x 32.
__global__ void __launch_bounds__(256, 2) gemm1_mma(
    const float* __restrict__ x,  const float* __restrict__ w0,
    const float* __restrict__ w1, const float* __restrict__ s0,
    const float* __restrict__ s1)
{
    int tile = blockIdx.y;
    if (tile >= g_ntiles) return;
    int e  = g_tile_e[tile];
    int bx = blockIdx.x;

    extern __shared__ char smem[];
    uint32_t sb = smem_u32(smem);
    int tid = threadIdx.x, lane = tid & 31, wid = tid >> 5;
    int wr = wid >> 1, wc = wid & 1;

    // ---- A fill: flat float4 mapping, fully coalesced (4 lines / warp-ldg) ----
    const float* axp[4];
    uint32_t stsAoff[4];
    #pragma unroll
    for (int i = 0; i < 4; i++) {
        int idx = i * 256 + tid;
        int row = idx >> 3, slot = idx & 7;        // row 0..127, slot 0..7 (float4)
        int grow = g_rows[tile * BM + row];
        axp[i] = (grow >= 0) ? x + (size_t)grow * D_DIM + slot * 4 : (const float*)0;
        stsAoff[i] = (uint32_t)(row * ROWSTRIDE + slot * 8);
    }
    // ---- B fill: 64 rows x 4 k-quarters (coalesced) ----
    int rb = tid >> 2, kq = tid & 3;
    int dffcol = bx * 32 + (rb >> 1);
    const float* bwp = ((rb & 1) ? w1 : w0) + ((size_t)e * DFF_DIM + dffcol) * D_DIM + kq * 8;
    uint32_t stsB = (uint32_t)(rb * ROWSTRIDE + kq * 16);

    // ---- ldmatrix per-lane offsets ----
    int li = lane & 7;
    uint32_t offA = (uint32_t)((wr * 32 + ((lane >> 3) & 1) * 8 + li) * ROWSTRIDE
                               + ((lane >> 4) & 1) * 16);
    uint32_t offB = (uint32_t)((wc * 32 + ((lane >> 4) & 1) * 8 + li) * ROWSTRIDE
                               + ((lane >> 3) & 1) * 16);

    float acc[2][4][4];
    #pragma unroll
    for (int i = 0; i < 2; i++)
        #pragma unroll
        for (int j = 0; j < 4; j++)
            #pragma unroll
            for (int c = 0; c < 4; c++) acc[i][j][c] = 0.f;

    float4 rA[4], rB[2];
    auto ldg = [&](int k0) {
        #pragma unroll
        for (int i = 0; i < 4; i++)
            rA[i] = axp[i] ? *(const float4*)(axp[i] + k0) : make_float4(0.f, 0.f, 0.f, 0.f);
        rB[0] = *(const float4*)(bwp + k0);
        rB[1] = *(const float4*)(bwp + k0 + 4);
    };
    auto sts = [&](int st) {
        char* base = smem + st * STAGE1;
        #pragma unroll
        for (int i = 0; i < 4; i++) {
            uint2 hh, ll;
            cvt4(rA[i], hh, ll);
            *(uint2*)(base + A_HI + stsAoff[i]) = hh;
            *(uint2*)(base + A_LO + stsAoff[i]) = ll;
        }
        uint4 hh0, ll0;
        cvt8(rB[0], rB[1], hh0, ll0);
        *(uint4*)(base + B_HI + stsB) = hh0;
        *(uint4*)(base + B_LO + stsB) = ll0;
    };

    ldg(0); sts(0);
    __syncthreads();

    const int NKB = D_DIM / KBLK;   // 64
    for (int kb = 0; kb < NKB; kb++) {
        if (kb + 1 < NKB) ldg((kb + 1) * KBLK);
        uint32_t st = sb + (kb & 1) * STAGE1;
        #pragma unroll
        for (int s = 0; s < 2; s++) {
            uint32_t Ah[2][4], Al[2][4], Bh[2][4], Bl[2][4];
            #pragma unroll
            for (int nj = 0; nj < 2; nj++) {
                LDSM4(Bh[nj], st + B_HI + offB + nj * 16 * ROWSTRIDE + s * 32);
                LDSM4(Bl[nj], st + B_LO + offB + nj * 16 * ROWSTRIDE + s * 32);
            }
            #pragma unroll
            for (int mi = 0; mi < 2; mi++) {
                LDSM4(Ah[mi], st + A_HI + offA + mi * 16 * ROWSTRIDE + s * 32);
                LDSM4(Al[mi], st + A_LO + offA + mi * 16 * ROWSTRIDE + s * 32);
            }
            // pass-major order: same-acc reuse spaced by 8 MMAs
            #pragma unroll
            for (int mi = 0; mi < 2; mi++)
                #pragma unroll
                for (int nj = 0; nj < 2; nj++) {
                    MMA(acc[mi][nj*2],   Ah[mi], Bh[nj][0], Bh[nj][1]);
                    MMA(acc[mi][nj*2+1], Ah[mi], Bh[nj][2], Bh[nj][3]);
                }
            #pragma unroll
            for (int mi = 0; mi < 2; mi++)
                #pragma unroll
                for (int nj = 0; nj < 2; nj++) {
                    MMA(acc[mi][nj*2],   Ah[mi], Bl[nj][0], Bl[nj][1]);
                    MMA(acc[mi][nj*2+1], Ah[mi], Bl[nj][2], Bl[nj][3]);
                }
            #pragma unroll
            for (int mi = 0; mi < 2; mi++)
                #pragma unroll
                for (int nj = 0; nj < 2; nj++) {
                    MMA(acc[mi][nj*2],   Al[mi], Bh[nj][0], Bh[nj][1]);
                    MMA(acc[mi][nj*2+1], Al[mi], Bh[nj][2], Bh[nj][3]);
                }
        }
        if (kb + 1 < NKB) sts((kb + 1) & 1);
        __syncthreads();
    }

    // ---- epilogue: SwiGLU (c0=gate, c1=up of same dffcol), store H hi/lo ----
    float s0e = s0[e], s1e = s1[e];
    #pragma unroll
    for (int mi = 0; mi < 2; mi++)
        #pragma unroll
        for (int nf = 0; nf < 4; nf++) {
            int r0  = tile * BM + wr * 32 + mi * 16 + (lane >> 2);
            int col = bx * 32 + wc * 16 + nf * 4 + (lane & 3);
            float g0 = acc[mi][nf][0] * s0e, u0 = acc[mi][nf][1] * s1e;
            float g8 = acc[mi][nf][2] * s0e, u8 = acc[mi][nf][3] * s1e;
            float h0 = (g0 / (1.f + __expf(-g0))) * u0;
            float h8 = (g8 / (1.f + __expf(-g8))) * u8;
            size_t o0 = (size_t)r0 * DFF_DIM + col;
            size_t o8 = o0 + (size_t)8 * DFF_DIM;
            __nv_bfloat16 b0 = __float2bfloat16(h0);
            __nv_bfloat16 b8 = __float2bfloat16(h8);
            g_Hhi[o0] = b0; g_Hlo[o0] = __float2bfloat16(h0 - __bfloat162float(b0));
            g_Hhi[o8] = b8; g_Hlo[o8] = __float2bfloat16(h8 - __bfloat162float(b8));
        }
}

// ---------------- GEMM2: H @ w2^T * s2 -> Y ----------------
// CTA 128 rows x 64 d-cols. Warp grid 4x2, warp tile 32x32.
__global__ void __launch_bounds__(256, 2) gemm2_mma(
    const float* __restrict__ w2, const float* __restrict__ s2)
{
    int tile = blockIdx.y;
    if (tile >= g_ntiles) return;
    int e  = g_tile_e[tile];
    int bx = blockIdx.x;

    extern __shared__ char smem[];
    uint32_t sb = smem_u32(smem);
    int tid = threadIdx.x, lane = tid & 31, wid = tid >> 5;
    int wr = wid >> 1, wc = wid & 1;

    // ---- A fill (H bf16 hi/lo): flat uint4 mapping ----
    const __nv_bfloat16* ahp[2];
    const __nv_bfloat16* alp[2];
    uint32_t stsAoff[2];
    #pragma unroll
    for (int i = 0; i < 2; i++) {
        int idx = i * 256 + tid;
        int row = idx >> 2, slot = idx & 3;        // row 0..127, slot 0..3 (uint4 = 8 bf16)
        size_t off = (size_t)(tile * BM + row) * DFF_DIM + slot * 8;
        ahp[i] = g_Hhi + off;
        alp[i] = g_Hlo + off;
        stsAoff[i] = (uint32_t)(row * ROWSTRIDE + slot * 16);
    }
    int rb = tid >> 2, kq = tid & 3;
    const float* bwp = w2 + ((size_t)e * D_DIM + bx * 64 + rb) * DFF_DIM + kq * 8;
    uint32_t stsB = (uint32_t)(rb * ROWSTRIDE + kq * 16);

    int li = lane & 7;
    uint32_t offA = (uint32_t)((wr * 32 + ((lane >> 3) & 1) * 8 + li) * ROWSTRIDE
                               + ((lane >> 4) & 1) * 16);
    uint32_t offB = (uint32_t)((wc * 32 + ((lane >> 4) & 1) * 8 + li) * ROWSTRIDE
                               + ((lane >> 3) & 1) * 16);

    float acc[2][4][4];
    #pragma unroll
    for (int i = 0; i < 2; i++)
        #pragma unroll
        for (int j = 0; j < 4; j++)
            #pragma unroll
            for (int c = 0; c < 4; c++) acc[i][j][c] = 0.f;

    uint4 hA[2], lA[2];
    float4 rB[2];
    auto ldg = [&](int k0) {
        #pragma unroll
        for (int i = 0; i < 2; i++) {
            hA[i] = *(const uint4*)(ahp[i] + k0);
            lA[i] = *(const uint4*)(alp[i] + k0);
        }
        rB[0] = *(const float4*)(bwp + k0);
        rB[1] = *(const float4*)(bwp + k0 + 4);
    };
    auto sts = [&](int st) {
        char* base = smem + st * STAGE1;
        #pragma unroll
        for (int i = 0; i < 2; i++) {
            *(uint4*)(base + A_HI + stsAoff[i]) = hA[i];
            *(uint4*)(base + A_LO + stsAoff[i]) = lA[i];
        }
        uint4 hh0, ll0;
        cvt8(rB[0], rB[1], hh0, ll0);
        *(uint4*)(base + B_HI + stsB) = hh0;
        *(uint4*)(base + B_LO + stsB) = ll0;
    };

    ldg(0); sts(0);
    __syncthreads();

    const int NKB = DFF_DIM / KBLK;   // 32
    for (int kb = 0; kb < NKB; kb++) {
        if (kb + 1 < NKB) ldg((kb + 1) * KBLK);
        uint32_t st = sb + (kb & 1) * STAGE1;
        #pragma unroll
        for (int s = 0; s < 2; s++) {
            uint32_t Ah[2][4], Al[2][4], Bh[2][4], Bl[2][4];
            #pragma unroll
            for (int nj = 0; nj < 2; nj++) {
                LDSM4(Bh[nj], st + B_HI + offB + nj * 16 * ROWSTRIDE + s * 32);
                LDSM4(Bl[nj], st + B_LO + offB + nj * 16 * ROWSTRIDE + s * 32);
            }
            #pragma unroll
            for (int mi = 0; mi < 2; mi++) {
                LDSM4(Ah[mi], st + A_HI + offA + mi * 16 * ROWSTRIDE + s * 32);
                LDSM4(Al[mi], st + A_LO + offA + mi * 16 * ROWSTRIDE + s * 32);
            }
            #pragma unroll
            for (int mi = 0; mi < 2; mi++)
                #pragma unroll
                for (int nj = 0; nj < 2; nj++) {
                    MMA(acc[mi][nj*2],   Ah[mi], Bh[nj][0], Bh[nj][1]);
                    MMA(acc[mi][nj*2+1], Ah[mi], Bh[nj][2], Bh[nj][3]);
                }
            #pragma unroll
            for (int mi = 0; mi < 2; mi++)
                #pragma unroll
                for (int nj = 0; nj < 2; nj++) {
                    MMA(acc[mi][nj*2],   Ah[mi], Bl[nj][0], Bl[nj][1]);
                    MMA(acc[mi][nj*2+1], Ah[mi], Bl[nj][2], Bl[nj][3]);
                }
            #pragma unroll
            for (int mi = 0; mi < 2; mi++)
                #pragma unroll
                for (int nj = 0; nj < 2; nj++) {
                    MMA(acc[mi][nj*2],   Al[mi], Bh[nj][0], Bh[nj][1]);
                    MMA(acc[mi][nj*2+1], Al[mi], Bh[nj][2], Bh[nj][3]);
                }
        }
        if (kb + 1 < NKB) sts((kb + 1) & 1);
        __syncthreads();
    }

    float s2e = s2[e];
    #pragma unroll
    for (int mi = 0; mi < 2; mi++)
        #pragma unroll
        for (int nf = 0; nf < 4; nf++) {
            int r0  = tile * BM + wr * 32 + mi * 16 + (lane >> 2);
            int col = bx * 64 + wc * 32 + nf * 8 + 2 * (lane & 3);
            float2 v0 = make_float2(acc[mi][nf][0] * s2e, acc[mi][nf][1] * s2e);
            float2 v8 = make_float2(acc[mi][nf][2] * s2e, acc[mi][nf][3] * s2e);
            *(float2*)(g_Y + (size_t)r0 * D_DIM + col) = v0;
            *(float2*)(g_Y + (size_t)(r0 + 8) * D_DIM + col) = v8;
        }
}

// ---------------- final gather: out[t] = sum_k rw[t,k] * Y[slot(t,k)] ----------------
__global__ void gather_kernel(float* __restrict__ out, const float* __restrict__ rw) {
    int idx = blockIdx.x * blockDim.x + threadIdx.x;
    int t = idx >> 9;
    int q = (idx & 511) * 4;
    float4 acc = make_float4(0.f, 0.f, 0.f, 0.f);
    #pragma unroll
    for (int k = 0; k < K_TOP; k++) {
        int p = t * K_TOP + k;
        float w = rw[p];
        const float4 v = *(const float4*)(g_Y + (size_t)g_slot[p] * D_DIM + q);
        acc.x += w * v.x; acc.y += w * v.y; acc.z += w * v.z; acc.w += w * v.w;
    }
    *(float4*)(out + (size_t)t * D_DIM + q) = acc;
}

// ---------------- launch ----------------
extern "C" void kernel_launch(void* const* d_in, const int* in_sizes, int n_in,
                              void* d_out, int out_size) {
    const float* x   = (const float*)d_in[0];
    const float* w0  = (const float*)d_in[1];
    const float* w1  = (const float*)d_in[2];
    const float* w2  = (const float*)d_in[3];
    const float* s0  = (const float*)d_in[4];
    const float* s1  = (const float*)d_in[5];
    const float* s2  = (const float*)d_in[6];
    const void*  sel = d_in[7];
    const float* rw  = (const float*)d_in[8];
    float* out = (float*)d_out;

    cudaFuncSetAttribute(gemm1_mma, cudaFuncAttributeMaxDynamicSharedMemorySize, SMEM_BYTES);
    cudaFuncSetAttribute(gemm2_mma, cudaFuncAttributeMaxDynamicSharedMemorySize, SMEM_BYTES);

    prep0_kernel<<<(P_PAD + 255) / 256, 256>>>(sel);
    count_kernel<<<(P_PAIR + 255) / 256, 256>>>(sel);
    setup_fill_kernel<<<1, 256>>>(sel);
    gemm1_mma<<<dim3(DFF_DIM / 32, MAX_TILES), 256, SMEM_BYTES>>>(x, w0, w1, s0, s1);
    gemm2_mma<<<dim3(D_DIM / 64, MAX_TILES), 256, SMEM_BYTES>>>(w2, s2);
    gather_kernel<<<(T_TOK * 512) / 256, 256>>>(out, rw);
}